// round 5
// baseline (speedup 1.0000x reference)
#include <cuda_runtime.h>

#define N_NODES 100000
#define N_EDGES 3200000
#define IN_CH   128
#define HID     64
#define N_GRAPHS 64

// Scratch (no allocations allowed): ping-pong feature buffers + pool accumulators
__device__ float g_bufA[(size_t)N_NODES * HID];   // 25.6 MB
__device__ float g_bufB[(size_t)N_NODES * HID];   // 25.6 MB
__device__ float g_pool[N_GRAPHS * HID + N_GRAPHS]; // sums[4096] then counts[64]

// ---------------------------------------------------------------------------
// Zero kernels (graph-capturable, no memsets)
// ---------------------------------------------------------------------------
__global__ void zero_bufB_kernel() {
    int i = blockIdx.x * blockDim.x + threadIdx.x;            // n4 = 1.6M
    ((float4*)g_bufB)[i] = make_float4(0.f, 0.f, 0.f, 0.f);
}

__global__ void zero_pool_kernel() {
    int i = blockIdx.x * blockDim.x + threadIdx.x;
    int n4 = (N_GRAPHS * HID + N_GRAPHS) / 4;                 // 1040
    if (i < n4) ((float4*)g_pool)[i] = make_float4(0.f, 0.f, 0.f, 0.f);
}

// ---------------------------------------------------------------------------
// GEMM1: g_bufA = x @ W1   (100000x128 @ 128x64), fp32
// Block: 128 threads = 16 rows x 8 col-groups (8 cols each)
// ---------------------------------------------------------------------------
__global__ __launch_bounds__(128) void gemm1_kernel(const float* __restrict__ x,
                                                    const float* __restrict__ W1) {
    __shared__ float xs[16][129];        // padded: conflict-free row reads
    __shared__ float ws[IN_CH][HID];     // 32 KB
    const int tid  = threadIdx.x;
    const int row0 = blockIdx.x * 16;

    // Load W1 (8192 floats) via float4
    const float4* W4 = (const float4*)W1;
    #pragma unroll
    for (int i = tid; i < IN_CH * HID / 4; i += 128) {
        int f = i * 4;
        *(float4*)&ws[f / HID][f % HID] = W4[i];
    }
    // Load x tile (16 x 128)
    #pragma unroll
    for (int i = tid; i < 16 * (IN_CH / 4); i += 128) {
        int r  = i >> 5;            // 32 float4 per row
        int kq = (i & 31) * 4;
        float4 v = *(const float4*)&x[(size_t)(row0 + r) * IN_CH + kq];
        xs[r][kq] = v.x; xs[r][kq + 1] = v.y; xs[r][kq + 2] = v.z; xs[r][kq + 3] = v.w;
    }
    __syncthreads();

    const int c = tid >> 4;   // 0..7 col-group
    const int r = tid & 15;   // 0..15 row
    float acc[8];
    #pragma unroll
    for (int j = 0; j < 8; j++) acc[j] = 0.f;

    #pragma unroll 8
    for (int k = 0; k < IN_CH; k++) {
        float  xv = xs[r][k];
        float4 w0 = *(float4*)&ws[k][c * 8];
        float4 w1 = *(float4*)&ws[k][c * 8 + 4];
        acc[0] += xv * w0.x; acc[1] += xv * w0.y; acc[2] += xv * w0.z; acc[3] += xv * w0.w;
        acc[4] += xv * w1.x; acc[5] += xv * w1.y; acc[6] += xv * w1.z; acc[7] += xv * w1.w;
    }
    float* o = &g_bufA[(size_t)(row0 + r) * HID + c * 8];
    *(float4*)o       = make_float4(acc[0], acc[1], acc[2], acc[3]);
    *(float4*)(o + 4) = make_float4(acc[4], acc[5], acc[6], acc[7]);
}

// ---------------------------------------------------------------------------
// GEMM2: g_bufA = relu(g_bufB + b1) @ W2   (100000x64 @ 64x64)
// (layer-1 ReLU+bias fused into the shared-memory tile load)
// ---------------------------------------------------------------------------
__global__ __launch_bounds__(128) void gemm2_kernel(const float* __restrict__ W2,
                                                    const float* __restrict__ b1) {
    __shared__ float xs[16][65];
    __shared__ float ws[HID][HID];       // 16 KB
    const int tid  = threadIdx.x;
    const int row0 = blockIdx.x * 16;

    const float4* W4 = (const float4*)W2;
    #pragma unroll
    for (int i = tid; i < HID * HID / 4; i += 128) {
        int f = i * 4;
        *(float4*)&ws[f / HID][f % HID] = W4[i];
    }
    #pragma unroll
    for (int i = tid; i < 16 * HID; i += 128) {
        int r = i >> 6;
        int k = i & 63;
        float v = g_bufB[(size_t)(row0 + r) * HID + k] + b1[k];
        xs[r][k] = fmaxf(v, 0.f);
    }
    __syncthreads();

    const int c = tid >> 4;
    const int r = tid & 15;
    float acc[8];
    #pragma unroll
    for (int j = 0; j < 8; j++) acc[j] = 0.f;

    #pragma unroll 8
    for (int k = 0; k < HID; k++) {
        float  xv = xs[r][k];
        float4 w0 = *(float4*)&ws[k][c * 8];
        float4 w1 = *(float4*)&ws[k][c * 8 + 4];
        acc[0] += xv * w0.x; acc[1] += xv * w0.y; acc[2] += xv * w0.z; acc[3] += xv * w0.w;
        acc[4] += xv * w1.x; acc[5] += xv * w1.y; acc[6] += xv * w1.z; acc[7] += xv * w1.w;
    }
    float* o = &g_bufA[(size_t)(row0 + r) * HID + c * 8];
    *(float4*)o       = make_float4(acc[0], acc[1], acc[2], acc[3]);
    *(float4*)(o + 4) = make_float4(acc[4], acc[5], acc[6], acc[7]);
}

// ---------------------------------------------------------------------------
// Edge scatter: g_bufB[dst] += g_bufA[src] * ew
// 16 threads/edge (float4 lanes), 2 edges/warp. Only lanes 0 and 16 load the
// edge triple; broadcast via shuffle -> 16x fewer index LDGs.
// Indices are INT32 (JAX default x64-disabled downcasts int64 -> int32).
// Vector reduction (red.global.add.v4.f32) -> 4x fewer RED instructions.
// ---------------------------------------------------------------------------
__global__ __launch_bounds__(256) void scatter_kernel(const int* __restrict__ ei,
                                                      const float* __restrict__ ew) {
    int gt   = blockIdx.x * blockDim.x + threadIdx.x;   // up to 51.2M < 2^31
    int lane = threadIdx.x & 31;
    int sub  = lane >> 4;               // which of the warp's 2 edges
    int t    = lane & 15;               // float4 lane within the edge
    int e    = (gt >> 5) * 2 + sub;
    if (e >= N_EDGES) return;

    int src_l = 0, dst_l = 0; float w_l = 0.f;
    if (t == 0) {
        src_l = ei[e];
        dst_l = ei[N_EDGES + e];
        w_l   = ew[e];
    }
    int   src = __shfl_sync(0xffffffffu, src_l, sub << 4);
    int   dst = __shfl_sync(0xffffffffu, dst_l, sub << 4);
    float w   = __shfl_sync(0xffffffffu, w_l,   sub << 4);

    float4 v = *(const float4*)&g_bufA[(size_t)src * HID + t * 4];
    v.x *= w; v.y *= w; v.z *= w; v.w *= w;

    float* a = &g_bufB[(size_t)dst * HID + t * 4];
    asm volatile("red.global.add.v4.f32 [%0], {%1,%2,%3,%4};"
                 :: "l"(a), "f"(v.x), "f"(v.y), "f"(v.z), "f"(v.w)
                 : "memory");
}

// ---------------------------------------------------------------------------
// Pool: sums[g] += relu(g_bufB[n] + b2); counts[g] += 1   (16 threads/node,
// 2 nodes/warp, batch[] (int32) loaded once per node and shuffled)
// ---------------------------------------------------------------------------
__global__ __launch_bounds__(256) void pool_kernel(const int* __restrict__ batch,
                                                   const float* __restrict__ b2) {
    int gt   = blockIdx.x * blockDim.x + threadIdx.x;
    int lane = threadIdx.x & 31;
    int sub  = lane >> 4;
    int t    = lane & 15;
    int n    = (gt >> 5) * 2 + sub;
    if (n >= N_NODES) return;

    int g_l = 0;
    if (t == 0) g_l = batch[n];
    int g = __shfl_sync(0xffffffffu, g_l, sub << 4);

    float4 bv = *(const float4*)&b2[t * 4];
    float4 v  = *(const float4*)&g_bufB[(size_t)n * HID + t * 4];
    v.x = fmaxf(v.x + bv.x, 0.f);
    v.y = fmaxf(v.y + bv.y, 0.f);
    v.z = fmaxf(v.z + bv.z, 0.f);
    v.w = fmaxf(v.w + bv.w, 0.f);

    float* s = &g_pool[g * HID + t * 4];
    asm volatile("red.global.add.v4.f32 [%0], {%1,%2,%3,%4};"
                 :: "l"(s), "f"(v.x), "f"(v.y), "f"(v.z), "f"(v.w)
                 : "memory");
    if (t == 0) atomicAdd(&g_pool[N_GRAPHS * HID + g], 1.0f);
}

__global__ void finalize_kernel(float* __restrict__ out) {
    int i = blockIdx.x * blockDim.x + threadIdx.x;
    if (i < N_GRAPHS * HID) {
        float c = g_pool[N_GRAPHS * HID + (i >> 6)];
        out[i] = g_pool[i] / fmaxf(c, 1.0f);
    }
}

// ---------------------------------------------------------------------------
// Launch: identify inputs by element count (robust to metadata ordering);
// b1 precedes b2 in input order (both size 64).
// ---------------------------------------------------------------------------
extern "C" void kernel_launch(void* const* d_in, const int* in_sizes, int n_in,
                              void* d_out, int out_size) {
    const float *x = nullptr, *ew = nullptr, *W1 = nullptr, *b1 = nullptr,
                *W2 = nullptr, *b2 = nullptr;
    const int *ei = nullptr, *batch = nullptr;

    for (int i = 0; i < n_in; i++) {
        int s = in_sizes[i];
        if      (s == N_NODES * IN_CH) x     = (const float*)d_in[i];
        else if (s == 2 * N_EDGES)     ei    = (const int*)d_in[i];
        else if (s == N_EDGES)         ew    = (const float*)d_in[i];
        else if (s == N_NODES)         batch = (const int*)d_in[i];
        else if (s == IN_CH * HID)     W1    = (const float*)d_in[i];
        else if (s == HID * HID)       W2    = (const float*)d_in[i];
        else if (s == HID) { if (!b1) b1 = (const float*)d_in[i];
                             else     b2 = (const float*)d_in[i]; }
        // size-1 num_graphs: ignored (compile-time constant)
    }

    float* out = (float*)d_out;

    const int zeroB_blocks   = (N_NODES * HID / 4) / 256;          // 6250
    const int gemm_blocks    = N_NODES / 16;                       // 6250
    const int scatter_blocks = (N_EDGES * 16 + 255) / 256;         // 200000
    const int pool_blocks    = (N_NODES * 16 + 255) / 256;         // 6250

    // Layer 1
    gemm1_kernel<<<gemm_blocks, 128>>>(x, W1);
    zero_bufB_kernel<<<zeroB_blocks, 256>>>();
    scatter_kernel<<<scatter_blocks, 256>>>(ei, ew);
    // Layer 2 (consumes bufB, then bufB re-zeroed for second aggregation)
    gemm2_kernel<<<gemm_blocks, 128>>>(W2, b1);
    zero_bufB_kernel<<<zeroB_blocks, 256>>>();
    zero_pool_kernel<<<5, 256>>>();
    scatter_kernel<<<scatter_blocks, 256>>>(ei, ew);
    // Pool + finalize
    pool_kernel<<<pool_blocks, 256>>>(batch, b2);
    finalize_kernel<<<16, 256>>>(out);
}